// round 13
// baseline (speedup 1.0000x reference)
#include <cuda_runtime.h>
#include <math.h>
#include <stdint.h>

#define B_ROWS 16384
#define D_DIM  4096
#define H_DIM  128
#define E_DIM  64
#define NS     5

static constexpr float P_DROP = 0.3f;
static constexpr float SCALE  = (float)(1.0 / 0.7);
static constexpr float UNC_T  = 0.3f;

#define NT 512
#define BM 128
#define BK 32
#define NTILES (D_DIM / BK)     // 128

// ---- smem layout (float offsets) ----
#define APITCH   36                        // row pitch in float2 units (hi,lo interleaved)
#define A_BUF    9216                      // 128 rows * 36 * 2 floats
#define OFF_A    0                         // 2 buffers: 18432
#define B_BUF    8192                      // interleaved {bh0,bh1,bl0,bl1} per fragment-lane
#define OFF_B    18432                     // 2 buffers: 16384 -> ends 34816
#define PITCH2   132
#define OFF_SH   0                         // phase2: 128*132 = 16896 (aliases A)
#define OFF_HM   18432                     // 16896 -> ends 35328 (aliases B)
#define OFF_W2   35328                     // 8192
#define OFF_B1   43520                     // 128
#define OFF_B2   43648                     // 64
#define SMEM_FLOATS 43712
#define SMEM_BYTES  (SMEM_FLOATS * 4)      // 174848

typedef unsigned long long u64;

__device__ float Bg_g[(size_t)D_DIM * H_DIM * 2];   // W1 hi+lo interleaved, fragment-permuted

__device__ __forceinline__ float tf32_rna(float v) {
    uint32_t u;
    asm("cvt.rna.tf32.f32 %0, %1;" : "=r"(u) : "f"(v));
    return __uint_as_float(u);
}
__device__ __forceinline__ u64 pack2(float a) {
    u64 r;
    asm("mov.b64 %0, {%1, %1};" : "=l"(r) : "r"(__float_as_uint(a)));
    return r;
}
__device__ __forceinline__ u64 pack2f(float a, float b) {
    u64 r;
    asm("mov.b64 %0, {%1, %2};" : "=l"(r) : "r"(__float_as_uint(a)), "r"(__float_as_uint(b)));
    return r;
}
__device__ __forceinline__ void unpack2(u64 v, float& a, float& b) {
    unsigned lo, hi;
    asm("mov.b64 {%0, %1}, %2;" : "=r"(lo), "=r"(hi) : "l"(v));
    a = __uint_as_float(lo);
    b = __uint_as_float(hi);
}
__device__ __forceinline__ void fma2(u64& d, u64 a, u64 b) {
    asm("fma.rn.f32x2 %0, %1, %2, %0;" : "+l"(d) : "l"(a), "l"(b));
}
__device__ __forceinline__ void cpasync16(uint32_t dst, const float* src) {
    asm volatile("cp.async.cg.shared.global [%0], [%1], 16;" :: "r"(dst), "l"(src));
}
__device__ __forceinline__ void mma_tf32(float* c, const uint32_t* a, const uint32_t* b) {
    asm volatile(
        "mma.sync.aligned.m16n8k8.row.col.f32.tf32.tf32.f32 "
        "{%0,%1,%2,%3}, {%4,%5,%6,%7}, {%8,%9}, {%0,%1,%2,%3};"
        : "+f"(c[0]), "+f"(c[1]), "+f"(c[2]), "+f"(c[3])
        : "r"(a[0]), "r"(a[1]), "r"(a[2]), "r"(a[3]), "r"(b[0]), "r"(b[1]));
}

// W1[k][n] -> split tf32 hi/lo, interleaved fragment order:
// float4 slot per (frag, lane): {bh_reg0, bh_reg1, bl_reg0, bl_reg1}
// frag = (k/8)*16 + n/8 ; lane = (n%8)*4 + (k%4) ; reg = (k%8)/4
__global__ void prep_b_kernel(const float* __restrict__ W1) {
    int idx = blockIdx.x * blockDim.x + threadIdx.x;   // 0..524287
    int k = idx >> 7, n = idx & 127;
    float v  = W1[idx];
    float hi = tf32_rna(v);
    float lo = tf32_rna(v - hi);
    int t_k = k >> 3, kk = k & 7, t_n = n >> 3, nn = n & 7;
    size_t base = ((size_t)(t_k * 16 + t_n) * 32 + (nn * 4 + (kk & 3))) * 4 + (kk >> 2);
    Bg_g[base]     = hi;
    Bg_g[base + 2] = lo;
}

__global__ __launch_bounds__(NT)
void bayes_route_kernel(const float* __restrict__ x,
                        const float* __restrict__ b1,
                        const float* __restrict__ W2,
                        const float* __restrict__ b2,
                        const float* __restrict__ m1u,
                        const float* __restrict__ m2u,
                        float* __restrict__ out)
{
    extern __shared__ __align__(16) float smem[];
    float* sH  = smem + OFF_SH;
    float* hMr = smem + OFF_HM;
    float* sW2 = smem + OFF_W2;
    float* sB1 = smem + OFF_B1;
    float* sB2 = smem + OFF_B2;

    const int tid  = threadIdx.x;
    const int lane = tid & 31;
    const int wid  = tid >> 5;        // 0..15
    const int warp_m = wid & 7;       // 8 warp rows x 16
    const int warp_n = wid >> 3;      // 2 warp cols x 64
    const int tx = tid & 15;
    const int ty = tid >> 4;          // 0..31
    const int ro = ty * 4;            // 4 rows per thread (phase 2)
    const int rowBase = blockIdx.x * BM;

    const uint32_t smem_u32 = (uint32_t)__cvta_generic_to_shared(smem);

    if (tid < H_DIM) sB1[tid] = b1[tid];
    if (tid < E_DIM) sB2[tid] = b2[tid];

    const float* xp = x + (size_t)rowBase * D_DIM;

    // per-thread x-load coordinates (2 float4 per tile)
    int xrow[2], xk4[2];
    #pragma unroll
    for (int i = 0; i < 2; i++) {
        int f = tid + (i << 9);
        xrow[i] = f >> 3;
        xk4[i]  = (f & 7) * 4;
    }

    auto ldg_x = [&](int t, float4* px) {
        int kt = t * BK;
        #pragma unroll
        for (int i = 0; i < 2; i++)
            px[i] = *(const float4*)(xp + (size_t)xrow[i] * D_DIM + kt + xk4[i]);
    };
    // A interleaved: float2 {hi, lo} at (row*APITCH + k)
    auto sts_x = [&](const float4* px, int buf) {
        float2* Ai = (float2*)(smem + OFF_A + buf * A_BUF);
        #pragma unroll
        for (int i = 0; i < 2; i++) {
            float4 v = px[i];
            const float vv[4] = {v.x, v.y, v.z, v.w};
            #pragma unroll
            for (int j = 0; j < 4; j++) {
                float hi = tf32_rna(vv[j]);
                float lo = tf32_rna(vv[j] - hi);
                Ai[xrow[i] * APITCH + xk4[i] + j] = make_float2(hi, lo);
            }
        }
    };
    auto fill_B = [&](int t, int buf) {
        uint32_t bs = smem_u32 + (OFF_B + buf * B_BUF) * 4;
        const float* gb = Bg_g + (size_t)t * 8192;
        #pragma unroll
        for (int i = 0; i < 4; i++) {
            int f = (tid + (i << 9)) * 4;      // float offset, 16B granules
            cpasync16(bs + f * 4, gb + f);
        }
        asm volatile("cp.async.commit_group;");
    };

    float acc[8][4];
    #pragma unroll
    for (int j = 0; j < 8; j++)
        #pragma unroll
        for (int q = 0; q < 4; q++) acc[j][q] = 0.f;

    // prologue: tiles 0,1 staged; prefetch x for tile 2
    float4 px[2];
    ldg_x(0, px); sts_x(px, 0); fill_B(0, 0);
    ldg_x(1, px); sts_x(px, 1); fill_B(1, 1);
    ldg_x(2, px);

    #pragma unroll 1
    for (int t = 0; t < NTILES; t++) {
        if (t < NTILES - 2) { asm volatile("cp.async.wait_group 1;"); }
        else                { asm volatile("cp.async.wait_group 0;"); }
        __syncthreads();

        const int buf = t & 1;
        const float2* Ai = (const float2*)(smem + OFF_A + buf * A_BUF);
        const float4* Bq = (const float4*)(smem + OFF_B + buf * B_BUF);

        #pragma unroll
        for (int k8 = 0; k8 < 4; k8++) {
            uint32_t ahi[4], alo[4];
            const int c0 = k8 * 8 + (lane & 3);
            const int r0 = warp_m * 16 + (lane >> 2);
            float2 a0 = Ai[r0 * APITCH + c0];
            float2 a1 = Ai[(r0 + 8) * APITCH + c0];
            float2 a2 = Ai[r0 * APITCH + c0 + 4];
            float2 a3 = Ai[(r0 + 8) * APITCH + c0 + 4];
            ahi[0] = __float_as_uint(a0.x); alo[0] = __float_as_uint(a0.y);
            ahi[1] = __float_as_uint(a1.x); alo[1] = __float_as_uint(a1.y);
            ahi[2] = __float_as_uint(a2.x); alo[2] = __float_as_uint(a2.y);
            ahi[3] = __float_as_uint(a3.x); alo[3] = __float_as_uint(a3.y);
            #pragma unroll
            for (int j = 0; j < 8; j++) {
                int tn = warp_n * 8 + j;
                float4 bv = Bq[(k8 * 16 + tn) * 32 + lane];
                uint32_t bhr[2] = {__float_as_uint(bv.x), __float_as_uint(bv.y)};
                uint32_t blr[2] = {__float_as_uint(bv.z), __float_as_uint(bv.w)};
                mma_tf32(acc[j], ahi, bhr);
                mma_tf32(acc[j], ahi, blr);
                mma_tf32(acc[j], alo, bhr);
            }
        }
        __syncthreads();
        if (t + 2 < NTILES) sts_x(px, buf);
        if (t + 3 < NTILES) ldg_x(t + 3, px);
        if (t + 2 < NTILES) fill_B(t + 2, buf);
    }

    // ---- epilogue: bias + relu -> sH (aliases dead A buffers) ----
    #pragma unroll
    for (int j = 0; j < 8; j++) {
        int row = warp_m * 16 + (lane >> 2);
        int col = warp_n * 64 + j * 8 + (lane & 3) * 2;
        float ba = sB1[col], bb = sB1[col + 1];
        *(float2*)(sH + row * PITCH2 + col) =
            make_float2(fmaxf(acc[j][0] + ba, 0.f), fmaxf(acc[j][1] + bb, 0.f));
        *(float2*)(sH + (row + 8) * PITCH2 + col) =
            make_float2(fmaxf(acc[j][2] + ba, 0.f), fmaxf(acc[j][3] + bb, 0.f));
    }
    // W2 k-major into smem
    {
        const float4* w2v = (const float4*)W2;
        float4* sv = (float4*)sW2;
        #pragma unroll
        for (int i = 0; i < (H_DIM * E_DIM) / 4 / NT; i++)
            sv[tid + i * NT] = w2v[tid + i * NT];
    }

    // =========================== Phase 2: 5 samples (FFMA2) ===========================
    const int e0 = tx * 4;

    float sumL[4][4], sumP[4][4], sumP2[4][4];
    #pragma unroll
    for (int i = 0; i < 4; i++)
        #pragma unroll
        for (int j = 0; j < 4; j++) { sumL[i][j] = 0.f; sumP[i][j] = 0.f; sumP2[i][j] = 0.f; }

    const u64 ib0 = pack2f(sB2[e0], sB2[e0 + 1]);
    const u64 ib1 = pack2f(sB2[e0 + 2], sB2[e0 + 3]);

    for (int s = 0; s < NS; s++) {
        __syncthreads();   // sH/W2 stores (s=0) or previous GEMM reads (s>0) complete
        {
            const float4* m1base = (const float4*)(m1u + ((size_t)s * B_ROWS + rowBase) * H_DIM);
            #pragma unroll
            for (int it = 0; it < 8; it++) {
                int idx = tid + it * NT;      // 0..4095 float4s
                int row = idx >> 5;
                int c4  = (idx & 31) * 4;
                float4 mu = m1base[idx];
                float4 hv = *(const float4*)(sH + row * PITCH2 + c4);
                float4 o;
                o.x = (mu.x >= P_DROP) ? hv.x * SCALE : 0.f;
                o.y = (mu.y >= P_DROP) ? hv.y * SCALE : 0.f;
                o.z = (mu.z >= P_DROP) ? hv.z * SCALE : 0.f;
                o.w = (mu.w >= P_DROP) ? hv.w * SCALE : 0.f;
                *(float4*)(hMr + row * PITCH2 + c4) = o;
            }
        }
        __syncthreads();

        u64 lacc[4][2];
        #pragma unroll
        for (int i = 0; i < 4; i++) { lacc[i][0] = ib0; lacc[i][1] = ib1; }

        #pragma unroll 4
        for (int k4 = 0; k4 < H_DIM; k4 += 4) {
            float4 af[4];
            #pragma unroll
            for (int i = 0; i < 4; i++)
                af[i] = *(const float4*)(hMr + (ro + i) * PITCH2 + k4);
            #pragma unroll
            for (int kk = 0; kk < 4; kk++) {
                ulonglong2 bb = *(const ulonglong2*)(sW2 + (k4 + kk) * E_DIM + e0);
                const float* afp = (const float*)af;
                #pragma unroll
                for (int i = 0; i < 4; i++) {
                    u64 aa = pack2(afp[i * 4 + kk]);
                    fma2(lacc[i][0], aa, bb.x);
                    fma2(lacc[i][1], aa, bb.y);
                }
            }
        }

        #pragma unroll
        for (int i = 0; i < 4; i++) {
            size_t row = (size_t)rowBase + ro + i;
            float4 mu = *(const float4*)(m2u + ((size_t)s * B_ROWS + row) * E_DIM + e0);
            float l[4];
            unpack2(lacc[i][0], l[0], l[1]);
            unpack2(lacc[i][1], l[2], l[3]);
            l[0] *= (mu.x >= P_DROP) ? SCALE : 0.f;
            l[1] *= (mu.y >= P_DROP) ? SCALE : 0.f;
            l[2] *= (mu.z >= P_DROP) ? SCALE : 0.f;
            l[3] *= (mu.w >= P_DROP) ? SCALE : 0.f;
            float mx = fmaxf(fmaxf(l[0], l[1]), fmaxf(l[2], l[3]));
            #pragma unroll
            for (int j = 0; j < 4; j++) sumL[i][j] += l[j];
            #pragma unroll
            for (int off = 1; off < 16; off <<= 1)
                mx = fmaxf(mx, __shfl_xor_sync(0xFFFFFFFFu, mx, off));
            float ex[4];
            float ss = 0.f;
            #pragma unroll
            for (int j = 0; j < 4; j++) { ex[j] = __expf(l[j] - mx); ss += ex[j]; }
            #pragma unroll
            for (int off = 1; off < 16; off <<= 1)
                ss += __shfl_xor_sync(0xFFFFFFFFu, ss, off);
            float inv = 1.f / ss;
            #pragma unroll
            for (int j = 0; j < 4; j++) {
                float pe = ex[j] * inv;
                sumP[i][j] += pe;
                sumP2[i][j] = fmaf(pe, pe, sumP2[i][j]);
            }
        }
    }

    // ---- final: mean softmax, uncertainty, top-4 ----
    #pragma unroll
    for (int i = 0; i < 4; i++) {
        float p[4];
        float mx = -1e30f;
        #pragma unroll
        for (int j = 0; j < 4; j++) { p[j] = sumL[i][j] * 0.2f; mx = fmaxf(mx, p[j]); }
        #pragma unroll
        for (int off = 1; off < 16; off <<= 1)
            mx = fmaxf(mx, __shfl_xor_sync(0xFFFFFFFFu, mx, off));
        float ss = 0.f;
        #pragma unroll
        for (int j = 0; j < 4; j++) { p[j] = __expf(p[j] - mx); ss += p[j]; }
        #pragma unroll
        for (int off = 1; off < 16; off <<= 1)
            ss += __shfl_xor_sync(0xFFFFFFFFu, ss, off);
        float inv = 1.f / ss;
        #pragma unroll
        for (int j = 0; j < 4; j++) p[j] *= inv;

        float us = 0.f;
        #pragma unroll
        for (int j = 0; j < 4; j++) {
            float mean = sumP[i][j] * 0.2f;
            float var  = (sumP2[i][j] - 5.f * mean * mean) * 0.25f;
            us += sqrtf(fmaxf(var, 0.f));
        }
        #pragma unroll
        for (int off = 1; off < 16; off <<= 1)
            us += __shfl_xor_sync(0xFFFFFFFFu, us, off);
        float unc = us * (1.f / 64.f);

        float fv[4];
        int   fi[4];
        #pragma unroll
        for (int t = 0; t < 4; t++) {
            float bv = p[0]; int bi = e0;
            #pragma unroll
            for (int j = 1; j < 4; j++)
                if (p[j] > bv) { bv = p[j]; bi = e0 + j; }
            #pragma unroll
            for (int off = 1; off < 16; off <<= 1) {
                float ov = __shfl_xor_sync(0xFFFFFFFFu, bv, off);
                int   oi = __shfl_xor_sync(0xFFFFFFFFu, bi, off);
                if (ov > bv || (ov == bv && oi < bi)) { bv = ov; bi = oi; }
            }
            fv[t] = bv; fi[t] = bi;
            #pragma unroll
            for (int j = 0; j < 4; j++)
                if (e0 + j == bi) p[j] = -2.f;
        }

        if (tx == 0) {
            size_t grow = (size_t)rowBase + ro + i;
            bool uncertain = unc > UNC_T;
            float* oIdx = out;
            float* oP   = out + (size_t)B_ROWS * 4;
            float* oU   = out + (size_t)B_ROWS * 8;
            oIdx[grow * 4 + 0] = (float)fi[0];
            oIdx[grow * 4 + 1] = (float)fi[1];
            oIdx[grow * 4 + 2] = uncertain ? (float)fi[2] : -1.f;
            oIdx[grow * 4 + 3] = uncertain ? (float)fi[3] : -1.f;
            oP[grow * 4 + 0] = fv[0];
            oP[grow * 4 + 1] = fv[1];
            oP[grow * 4 + 2] = uncertain ? fv[2] : 0.f;
            oP[grow * 4 + 3] = uncertain ? fv[3] : 0.f;
            oU[grow] = unc;
        }
    }
}

extern "C" void kernel_launch(void* const* d_in, const int* in_sizes, int n_in,
                              void* d_out, int out_size)
{
    (void)in_sizes; (void)n_in; (void)out_size;
    const float* x   = (const float*)d_in[0];
    const float* W1  = (const float*)d_in[1];
    const float* b1  = (const float*)d_in[2];
    const float* W2  = (const float*)d_in[3];
    const float* b2  = (const float*)d_in[4];
    const float* m1u = (const float*)d_in[5];
    const float* m2u = (const float*)d_in[6];
    float* out = (float*)d_out;

    prep_b_kernel<<<(D_DIM * H_DIM) / 256, 256>>>(W1);

    cudaFuncSetAttribute(bayes_route_kernel,
                         cudaFuncAttributeMaxDynamicSharedMemorySize, SMEM_BYTES);
    bayes_route_kernel<<<B_ROWS / BM, NT, SMEM_BYTES>>>(
        x, b1, W2, b2, m1u, m2u, out);
}

// round 14
// speedup vs baseline: 1.1440x; 1.1440x over previous
#include <cuda_runtime.h>
#include <math.h>
#include <stdint.h>

#define B_ROWS 16384
#define D_DIM  4096
#define H_DIM  128
#define E_DIM  64
#define NS     5

static constexpr float P_DROP = 0.3f;
static constexpr float SCALE  = (float)(1.0 / 0.7);
static constexpr float UNC_T  = 0.3f;

#define NT 512
#define BM 128
#define BK 32
#define NTILES (D_DIM / BK)     // 128
#define NBUF 3

// ---- smem layout (float offsets) ----
#define APITCH   36
#define ATILE    (128 * APITCH)            // 4608 (one of hi/lo)
#define A_BUF    (2 * ATILE)               // 9216 per buffer (hi+lo)
#define OFF_A    0                         // 3 buffers: 27648
#define B_BUF    8192                      // per buffer (hi 4096 + lo 4096)
#define OFF_B    27648                     // 3 buffers: 24576 -> ends 52224
#define PITCH2   132
#define OFF_SH   0                         // phase2: 128*132 = 16896 (aliases A bufs)
#define OFF_W2   16896                     // 8192 -> ends 25088 (aliases A bufs)
#define OFF_HM   OFF_B                     // 16896 (aliases B bufs)
#define OFF_B1   52224                     // 128
#define OFF_B2   52352                     // 64
#define SMEM_FLOATS 52416
#define SMEM_BYTES  (SMEM_FLOATS * 4)      // 209664 B

typedef unsigned long long u64;

__device__ float Bhi_g[(size_t)D_DIM * H_DIM];   // W1 hi, fragment-permuted
__device__ float Blo_g[(size_t)D_DIM * H_DIM];   // W1 lo

__device__ __forceinline__ float tf32_rna(float v) {
    uint32_t u;
    asm("cvt.rna.tf32.f32 %0, %1;" : "=r"(u) : "f"(v));
    return __uint_as_float(u);
}
__device__ __forceinline__ u64 pack2(float a) {
    u64 r;
    asm("mov.b64 %0, {%1, %1};" : "=l"(r) : "r"(__float_as_uint(a)));
    return r;
}
__device__ __forceinline__ u64 pack2f(float a, float b) {
    u64 r;
    asm("mov.b64 %0, {%1, %2};" : "=l"(r) : "r"(__float_as_uint(a)), "r"(__float_as_uint(b)));
    return r;
}
__device__ __forceinline__ void unpack2(u64 v, float& a, float& b) {
    unsigned lo, hi;
    asm("mov.b64 {%0, %1}, %2;" : "=r"(lo), "=r"(hi) : "l"(v));
    a = __uint_as_float(lo);
    b = __uint_as_float(hi);
}
__device__ __forceinline__ void fma2(u64& d, u64 a, u64 b) {
    asm("fma.rn.f32x2 %0, %1, %2, %0;" : "+l"(d) : "l"(a), "l"(b));
}
__device__ __forceinline__ void cpasync16(uint32_t dst, const float* src) {
    asm volatile("cp.async.cg.shared.global [%0], [%1], 16;" :: "r"(dst), "l"(src));
}
__device__ __forceinline__ void mma_tf32(float* c, const uint32_t* a, const uint32_t* b) {
    asm volatile(
        "mma.sync.aligned.m16n8k8.row.col.f32.tf32.tf32.f32 "
        "{%0,%1,%2,%3}, {%4,%5,%6,%7}, {%8,%9}, {%0,%1,%2,%3};"
        : "+f"(c[0]), "+f"(c[1]), "+f"(c[2]), "+f"(c[3])
        : "r"(a[0]), "r"(a[1]), "r"(a[2]), "r"(a[3]), "r"(b[0]), "r"(b[1]));
}

// W1[k][n] -> split tf32 hi/lo, permuted to fragment order:
// [t_k=k/8][t_n=n/8][lane=(n%8)*4+(k%4)][reg=(k%8)/4]
__global__ void prep_b_kernel(const float* __restrict__ W1) {
    int idx = blockIdx.x * blockDim.x + threadIdx.x;   // 0..524287
    int k = idx >> 7, n = idx & 127;
    float v  = W1[idx];
    float hi = tf32_rna(v);
    float lo = tf32_rna(v - hi);
    int t_k = k >> 3, kk = k & 7, t_n = n >> 3, nn = n & 7;
    size_t dst = ((size_t)(t_k * 16 + t_n) * 32 + (nn * 4 + (kk & 3))) * 2 + (kk >> 2);
    Bhi_g[dst] = hi;
    Blo_g[dst] = lo;
}

__global__ __launch_bounds__(NT)
void bayes_route_kernel(const float* __restrict__ x,
                        const float* __restrict__ b1,
                        const float* __restrict__ W2,
                        const float* __restrict__ b2,
                        const float* __restrict__ m1u,
                        const float* __restrict__ m2u,
                        float* __restrict__ out)
{
    extern __shared__ __align__(16) float smem[];
    float* sH  = smem + OFF_SH;
    float* hMr = smem + OFF_HM;
    float* sW2 = smem + OFF_W2;
    float* sB1 = smem + OFF_B1;
    float* sB2 = smem + OFF_B2;

    const int tid  = threadIdx.x;
    const int lane = tid & 31;
    const int wid  = tid >> 5;        // 0..15
    const int warp_m = wid & 7;       // 8 warp rows x 16
    const int warp_n = wid >> 3;      // 2 warp cols x 64
    const int tx = tid & 15;
    const int ty = tid >> 4;          // 0..31
    const int ro = ty * 4;            // 4 rows per thread (phase 2)
    const int rowBase = blockIdx.x * BM;

    const uint32_t smem_u32 = (uint32_t)__cvta_generic_to_shared(smem);

    if (tid < H_DIM) sB1[tid] = b1[tid];
    if (tid < E_DIM) sB2[tid] = b2[tid];

    const float* xp = x + (size_t)rowBase * D_DIM;

    // per-thread x-load coordinates (2 float4 per tile)
    int xrow[2], xk4[2];
    #pragma unroll
    for (int i = 0; i < 2; i++) {
        int f = tid + (i << 9);
        xrow[i] = f >> 3;
        xk4[i]  = (f & 7) * 4;
    }

    auto ldg_x = [&](int t, float4* px) {
        int kt = t * BK;
        #pragma unroll
        for (int i = 0; i < 2; i++)
            px[i] = *(const float4*)(xp + (size_t)xrow[i] * D_DIM + kt + xk4[i]);
    };
    auto sts_x = [&](const float4* px, int buf) {
        float* Ah = smem + OFF_A + buf * A_BUF;
        float* Al = Ah + ATILE;
        #pragma unroll
        for (int i = 0; i < 2; i++) {
            float4 v = px[i];
            float4 hi, lo;
            hi.x = tf32_rna(v.x); lo.x = tf32_rna(v.x - hi.x);
            hi.y = tf32_rna(v.y); lo.y = tf32_rna(v.y - hi.y);
            hi.z = tf32_rna(v.z); lo.z = tf32_rna(v.z - hi.z);
            hi.w = tf32_rna(v.w); lo.w = tf32_rna(v.w - hi.w);
            *(float4*)(Ah + xrow[i] * APITCH + xk4[i]) = hi;
            *(float4*)(Al + xrow[i] * APITCH + xk4[i]) = lo;
        }
    };
    auto fill_B = [&](int t, int buf) {
        uint32_t bh = smem_u32 + (OFF_B + buf * B_BUF) * 4;
        uint32_t bl = bh + 4096 * 4;
        const float* gh = Bhi_g + (size_t)t * 4096;
        const float* gl = Blo_g + (size_t)t * 4096;
        #pragma unroll
        for (int i = 0; i < 2; i++) {
            int f = (tid + (i << 9)) * 4;      // float offset, 16B granules
            cpasync16(bh + f * 4, gh + f);
            cpasync16(bl + f * 4, gl + f);
        }
        asm volatile("cp.async.commit_group;");
    };

    float acc[8][4];
    #pragma unroll
    for (int j = 0; j < 8; j++)
        #pragma unroll
        for (int q = 0; q < 4; q++) acc[j][q] = 0.f;

    // prologue: tiles 0,1 staged in bufs 0,1; prefetch x for tile 2
    float4 px[2];
    ldg_x(0, px); sts_x(px, 0); fill_B(0, 0);
    ldg_x(1, px); sts_x(px, 1); fill_B(1, 1);
    ldg_x(2, px);

    #pragma unroll 1
    for (int t = 0; t < NTILES; t++) {
        if (t < NTILES - 2) { asm volatile("cp.async.wait_group 1;"); }
        else                { asm volatile("cp.async.wait_group 0;"); }
        __syncthreads();    // single barrier per tile (NBUF=3 ring)

        const int buf = t % NBUF;
        const float* Ah = smem + OFF_A + buf * A_BUF;
        const float* Al = Ah + ATILE;
        const float2* Bh = (const float2*)(smem + OFF_B + buf * B_BUF);
        const float2* Bl = (const float2*)(smem + OFF_B + buf * B_BUF + 4096);

        #pragma unroll
        for (int k8 = 0; k8 < 4; k8++) {
            uint32_t ahi[4], alo[4];
            const int c0 = k8 * 8 + (lane & 3);
            const int r0 = warp_m * 16 + (lane >> 2);
            ahi[0] = __float_as_uint(Ah[r0 * APITCH + c0]);
            ahi[1] = __float_as_uint(Ah[(r0 + 8) * APITCH + c0]);
            ahi[2] = __float_as_uint(Ah[r0 * APITCH + c0 + 4]);
            ahi[3] = __float_as_uint(Ah[(r0 + 8) * APITCH + c0 + 4]);
            alo[0] = __float_as_uint(Al[r0 * APITCH + c0]);
            alo[1] = __float_as_uint(Al[(r0 + 8) * APITCH + c0]);
            alo[2] = __float_as_uint(Al[r0 * APITCH + c0 + 4]);
            alo[3] = __float_as_uint(Al[(r0 + 8) * APITCH + c0 + 4]);
            #pragma unroll
            for (int j = 0; j < 8; j++) {
                int tn = warp_n * 8 + j;
                float2 bhv = Bh[(k8 * 16 + tn) * 32 + lane];
                float2 blv = Bl[(k8 * 16 + tn) * 32 + lane];
                uint32_t bhr[2] = {__float_as_uint(bhv.x), __float_as_uint(bhv.y)};
                uint32_t blr[2] = {__float_as_uint(blv.x), __float_as_uint(blv.y)};
                mma_tf32(acc[j], ahi, bhr);
                mma_tf32(acc[j], ahi, blr);
                mma_tf32(acc[j], alo, bhr);
            }
        }

        // producer section: writes target buffer (t+2)%3, last read at t-1,
        // ordered by this tile's top barrier — no second barrier needed.
        if (t + 2 < NTILES) {
            const int nbuf = (t + 2) % NBUF;
            sts_x(px, nbuf);
            fill_B(t + 2, nbuf);
        }
        if (t + 3 < NTILES) ldg_x(t + 3, px);
    }
    __syncthreads();   // all MMA reads done before phase-2 regions overwrite the ring

    // ---- epilogue: bias + relu -> sH ----
    #pragma unroll
    for (int j = 0; j < 8; j++) {
        int row = warp_m * 16 + (lane >> 2);
        int col = warp_n * 64 + j * 8 + (lane & 3) * 2;
        float ba = sB1[col], bb = sB1[col + 1];
        *(float2*)(sH + row * PITCH2 + col) =
            make_float2(fmaxf(acc[j][0] + ba, 0.f), fmaxf(acc[j][1] + bb, 0.f));
        *(float2*)(sH + (row + 8) * PITCH2 + col) =
            make_float2(fmaxf(acc[j][2] + ba, 0.f), fmaxf(acc[j][3] + bb, 0.f));
    }
    // W2 k-major into smem
    {
        const float4* w2v = (const float4*)W2;
        float4* sv = (float4*)sW2;
        #pragma unroll
        for (int i = 0; i < (H_DIM * E_DIM) / 4 / NT; i++)
            sv[tid + i * NT] = w2v[tid + i * NT];
    }

    // =========================== Phase 2: 5 samples (FFMA2) ===========================
    const int e0 = tx * 4;

    float sumL[4][4], sumP[4][4], sumP2[4][4];
    #pragma unroll
    for (int i = 0; i < 4; i++)
        #pragma unroll
        for (int j = 0; j < 4; j++) { sumL[i][j] = 0.f; sumP[i][j] = 0.f; sumP2[i][j] = 0.f; }

    const u64 ib0 = pack2f(sB2[e0], sB2[e0 + 1]);
    const u64 ib1 = pack2f(sB2[e0 + 2], sB2[e0 + 3]);

    for (int s = 0; s < NS; s++) {
        __syncthreads();   // sH/W2 stores (s=0) or previous GEMM reads (s>0) complete
        {
            const float4* m1base = (const float4*)(m1u + ((size_t)s * B_ROWS + rowBase) * H_DIM);
            #pragma unroll
            for (int it = 0; it < 8; it++) {
                int idx = tid + it * NT;      // 0..4095 float4s
                int row = idx >> 5;
                int c4  = (idx & 31) * 4;
                float4 mu = m1base[idx];
                float4 hv = *(const float4*)(sH + row * PITCH2 + c4);
                float4 o;
                o.x = (mu.x >= P_DROP) ? hv.x * SCALE : 0.f;
                o.y = (mu.y >= P_DROP) ? hv.y * SCALE : 0.f;
                o.z = (mu.z >= P_DROP) ? hv.z * SCALE : 0.f;
                o.w = (mu.w >= P_DROP) ? hv.w * SCALE : 0.f;
                *(float4*)(hMr + row * PITCH2 + c4) = o;
            }
        }
        __syncthreads();

        u64 lacc[4][2];
        #pragma unroll
        for (int i = 0; i < 4; i++) { lacc[i][0] = ib0; lacc[i][1] = ib1; }

        #pragma unroll 4
        for (int k4 = 0; k4 < H_DIM; k4 += 4) {
            float4 af[4];
            #pragma unroll
            for (int i = 0; i < 4; i++)
                af[i] = *(const float4*)(hMr + (ro + i) * PITCH2 + k4);
            #pragma unroll
            for (int kk = 0; kk < 4; kk++) {
                ulonglong2 bb = *(const ulonglong2*)(sW2 + (k4 + kk) * E_DIM + e0);
                const float* afp = (const float*)af;
                #pragma unroll
                for (int i = 0; i < 4; i++) {
                    u64 aa = pack2(afp[i * 4 + kk]);
                    fma2(lacc[i][0], aa, bb.x);
                    fma2(lacc[i][1], aa, bb.y);
                }
            }
        }

        #pragma unroll
        for (int i = 0; i < 4; i++) {
            size_t row = (size_t)rowBase + ro + i;
            float4 mu = *(const float4*)(m2u + ((size_t)s * B_ROWS + row) * E_DIM + e0);
            float l[4];
            unpack2(lacc[i][0], l[0], l[1]);
            unpack2(lacc[i][1], l[2], l[3]);
            l[0] *= (mu.x >= P_DROP) ? SCALE : 0.f;
            l[1] *= (mu.y >= P_DROP) ? SCALE : 0.f;
            l[2] *= (mu.z >= P_DROP) ? SCALE : 0.f;
            l[3] *= (mu.w >= P_DROP) ? SCALE : 0.f;
            float mx = fmaxf(fmaxf(l[0], l[1]), fmaxf(l[2], l[3]));
            #pragma unroll
            for (int j = 0; j < 4; j++) sumL[i][j] += l[j];
            #pragma unroll
            for (int off = 1; off < 16; off <<= 1)
                mx = fmaxf(mx, __shfl_xor_sync(0xFFFFFFFFu, mx, off));
            float ex[4];
            float ss = 0.f;
            #pragma unroll
            for (int j = 0; j < 4; j++) { ex[j] = __expf(l[j] - mx); ss += ex[j]; }
            #pragma unroll
            for (int off = 1; off < 16; off <<= 1)
                ss += __shfl_xor_sync(0xFFFFFFFFu, ss, off);
            float inv = 1.f / ss;
            #pragma unroll
            for (int j = 0; j < 4; j++) {
                float pe = ex[j] * inv;
                sumP[i][j] += pe;
                sumP2[i][j] = fmaf(pe, pe, sumP2[i][j]);
            }
        }
    }

    // ---- final: mean softmax, uncertainty, top-4 ----
    #pragma unroll
    for (int i = 0; i < 4; i++) {
        float p[4];
        float mx = -1e30f;
        #pragma unroll
        for (int j = 0; j < 4; j++) { p[j] = sumL[i][j] * 0.2f; mx = fmaxf(mx, p[j]); }
        #pragma unroll
        for (int off = 1; off < 16; off <<= 1)
            mx = fmaxf(mx, __shfl_xor_sync(0xFFFFFFFFu, mx, off));
        float ss = 0.f;
        #pragma unroll
        for (int j = 0; j < 4; j++) { p[j] = __expf(p[j] - mx); ss += p[j]; }
        #pragma unroll
        for (int off = 1; off < 16; off <<= 1)
            ss += __shfl_xor_sync(0xFFFFFFFFu, ss, off);
        float inv = 1.f / ss;
        #pragma unroll
        for (int j = 0; j < 4; j++) p[j] *= inv;

        float us = 0.f;
        #pragma unroll
        for (int j = 0; j < 4; j++) {
            float mean = sumP[i][j] * 0.2f;
            float var  = (sumP2[i][j] - 5.f * mean * mean) * 0.25f;
            us += sqrtf(fmaxf(var, 0.f));
        }
        #pragma unroll
        for (int off = 1; off < 16; off <<= 1)
            us += __shfl_xor_sync(0xFFFFFFFFu, us, off);
        float unc = us * (1.f / 64.f);

        float fv[4];
        int   fi[4];
        #pragma unroll
        for (int t = 0; t < 4; t++) {
            float bv = p[0]; int bi = e0;
            #pragma unroll
            for (int j = 1; j < 4; j++)
                if (p[j] > bv) { bv = p[j]; bi = e0 + j; }
            #pragma unroll
            for (int off = 1; off < 16; off <<= 1) {
                float ov = __shfl_xor_sync(0xFFFFFFFFu, bv, off);
                int   oi = __shfl_xor_sync(0xFFFFFFFFu, bi, off);
                if (ov > bv || (ov == bv && oi < bi)) { bv = ov; bi = oi; }
            }
            fv[t] = bv; fi[t] = bi;
            #pragma unroll
            for (int j = 0; j < 4; j++)
                if (e0 + j == bi) p[j] = -2.f;
        }

        if (tx == 0) {
            size_t grow = (size_t)rowBase + ro + i;
            bool uncertain = unc > UNC_T;
            float* oIdx = out;
            float* oP   = out + (size_t)B_ROWS * 4;
            float* oU   = out + (size_t)B_ROWS * 8;
            oIdx[grow * 4 + 0] = (float)fi[0];
            oIdx[grow * 4 + 1] = (float)fi[1];
            oIdx[grow * 4 + 2] = uncertain ? (float)fi[2] : -1.f;
            oIdx[grow * 4 + 3] = uncertain ? (float)fi[3] : -1.f;
            oP[grow * 4 + 0] = fv[0];
            oP[grow * 4 + 1] = fv[1];
            oP[grow * 4 + 2] = uncertain ? fv[2] : 0.f;
            oP[grow * 4 + 3] = uncertain ? fv[3] : 0.f;
            oU[grow] = unc;
        }
    }
}

extern "C" void kernel_launch(void* const* d_in, const int* in_sizes, int n_in,
                              void* d_out, int out_size)
{
    (void)in_sizes; (void)n_in; (void)out_size;
    const float* x   = (const float*)d_in[0];
    const float* W1  = (const float*)d_in[1];
    const float* b1  = (const float*)d_in[2];
    const float* W2  = (const float*)d_in[3];
    const float* b2  = (const float*)d_in[4];
    const float* m1u = (const float*)d_in[5];
    const float* m2u = (const float*)d_in[6];
    float* out = (float*)d_out;

    prep_b_kernel<<<(D_DIM * H_DIM) / 256, 256>>>(W1);

    cudaFuncSetAttribute(bayes_route_kernel,
                         cudaFuncAttributeMaxDynamicSharedMemorySize, SMEM_BYTES);
    bayes_route_kernel<<<B_ROWS / BM, NT, SMEM_BYTES>>>(
        x, b1, W2, b2, m1u, m2u, out);
}